// round 14
// baseline (speedup 1.0000x reference)
#include <cuda_runtime.h>
#include <cuda_bf16.h>
#include <math.h>
#include <stdint.h>

// Linear_bin: binarized 5-layer MLP, B=32768, 64->2048->1024->512->64->1.
// L1: bf16 mma GEMM (exact 3-way split of x), epilogue emits s4 A-fragments.
// L2, L3: s4 mma.m16n8k64 GEMMs (exact: operands in {-1,0,1}/{0,1}),
//         zero-smem fragment mainloop (R7 structure, half the bytes/MMAs).
// L4+L5+sigmoid: fused popcount kernel.

#define BATCH 32768
#define EPSBN 1e-5f

// ---------------- scratch (static device globals; no allocation) ----------------
__device__ __align__(16) __nv_bfloat16 d_xp[BATCH * 192];     // x split: hi|mid|lo
__device__ __align__(16) unsigned short d_w1b[2048 * 192];    // sign(w1) bf16, 3x replicated
__device__ __align__(16) uint4 d_w2f[64 * 32 * 32];           // sign(w2) s4 B-frags [nq][kc][lane]
__device__ __align__(16) uint4 d_w3f[32 * 16 * 32];           // sign(w3) s4 B-frags
__device__ __align__(16) uint4 d_a1f[2048 * 32 * 32];         // L1 acts s4 A-frags (32MB)
__device__ __align__(16) uint4 d_a2f[2048 * 16 * 32];         // L2 acts s4 A-frags (16MB)
__device__ unsigned d_p4[64 * 16];
__device__ unsigned d_n4[64 * 16];
__device__ __align__(16) char  d_a3s[BATCH * 512];            // L3 acts {0,1} row-major
__device__ __align__(16) unsigned d_h3[BATCH * 16];           // L3 bits

// ---------------- helpers --------------------------------------------------------
__device__ __forceinline__ uint32_t smem_u32(const void* p) {
    uint32_t a;
    asm("{ .reg .u64 t; cvta.to.shared.u64 t, %1; cvt.u32.u64 %0, t; }" : "=r"(a) : "l"(p));
    return a;
}
#define LDMX4(r, a) \
    asm volatile("ldmatrix.sync.aligned.m8n8.x4.shared.b16 {%0,%1,%2,%3}, [%4];" \
        : "=r"((r)[0]), "=r"((r)[1]), "=r"((r)[2]), "=r"((r)[3]) : "r"(a))

__device__ __forceinline__ void mma_s4(int* c, const uint32_t* a, uint32_t b0, uint32_t b1) {
    asm volatile(
        "mma.sync.aligned.m16n8k64.row.col.s32.s4.s4.s32 "
        "{%0,%1,%2,%3}, {%4,%5,%6,%7}, {%8,%9}, {%0,%1,%2,%3};"
        : "+r"(c[0]), "+r"(c[1]), "+r"(c[2]), "+r"(c[3])
        : "r"(a[0]), "r"(a[1]), "r"(a[2]), "r"(a[3]), "r"(b0), "r"(b1));
}
__device__ __forceinline__ void mma_bf16(float* c, const uint32_t* a, uint32_t b0, uint32_t b1) {
    asm volatile(
        "mma.sync.aligned.m16n8k16.row.col.f32.bf16.bf16.f32 "
        "{%0,%1,%2,%3}, {%4,%5,%6,%7}, {%8,%9}, {%0,%1,%2,%3};"
        : "+f"(c[0]), "+f"(c[1]), "+f"(c[2]), "+f"(c[3])
        : "r"(a[0]), "r"(a[1]), "r"(a[2]), "r"(a[3]), "r"(b0), "r"(b1));
}
__device__ __forceinline__ void cp16(uint32_t dst, const void* src) {
    asm volatile("cp.async.cg.shared.global [%0], [%1], 16;" :: "r"(dst), "l"(src));
}
// 384-byte rows (K=192 bf16): swizzle within each 128B third
__device__ __forceinline__ uint32_t swz384(int r, int s) {
    return (uint32_t)(r * 384 + (((s & 24) | ((s ^ r) & 7)) << 4));
}
// 8 floats -> 8 s4 nibbles (sign): +1=0x1, -1=0xF, 0=0x0; nibble i = k offset i
__device__ __forceinline__ unsigned nib8(const float* p) {
    unsigned r = 0;
    #pragma unroll
    for (int j = 0; j < 8; j++) {
        float v = p[j];
        unsigned n = (v > 0.f) ? 0x1u : ((v < 0.f) ? 0xFu : 0x0u);
        r |= n << (4 * j);
    }
    return r;
}

// ---- s4 A-fragment emission: gather byte g of word w from 4 consecutive lanes ---
__device__ __forceinline__ unsigned gather_byte(unsigned w, int s0, int g) {
    unsigned x0 = __shfl_sync(0xffffffffu, w, s0);
    unsigned x1 = __shfl_sync(0xffffffffu, w, s0 + 1);
    unsigned x2 = __shfl_sync(0xffffffffu, w, s0 + 2);
    unsigned x3 = __shfl_sync(0xffffffffu, w, s0 + 3);
    unsigned selp = (unsigned)g | ((unsigned)(g + 4) << 4);
    unsigned lo = __byte_perm(x0, x1, selp);
    unsigned hi = __byte_perm(x2, x3, selp);
    return __byte_perm(lo, hi, 0x5410);
}
// wLoA: bytes nt0..3 (row rr, 2 nibbles each), wLoB: nt4..7, wHi*: row rr+8.
// Emits one m16n8k64 A-frag uint4 {a0,a1,a2,a3} covering 64 k-values x 16 rows.
__device__ __forceinline__ void emit_afrag4(
    uint4* dst, unsigned wLoA, unsigned wLoB, unsigned wHiA, unsigned wHiB, int lane)
{
    int s0 = lane & ~3, g = lane & 3;
    uint4 o;
    o.x = gather_byte(wLoA, s0, g);   // a0: row rr,   k 0..31
    o.y = gather_byte(wHiA, s0, g);   // a1: row rr+8, k 0..31
    o.z = gather_byte(wLoB, s0, g);   // a2: row rr,   k 32..63
    o.w = gather_byte(wHiB, s0, g);   // a3: row rr+8, k 32..63
    *dst = o;
}

// ---------------- weight preprocessing + x split ---------------------------------
// threads: w1b 131072 | xp 2097152 | w2f 65536 | w3f 16384 | w4 1024 = 2311168
__global__ void pack_all(const float* __restrict__ x,  const float* __restrict__ w1,
                         const float* __restrict__ w2, const float* __restrict__ w3,
                         const float* __restrict__ w4) {
    long idx = (long)blockIdx.x * 256 + threadIdx.x;
    if (idx < 131072) {                                  // sign(w1) bf16, replicated x3
        int n = (int)idx >> 6, k = (int)idx & 63;
        float v = w1[n * 64 + k];
        unsigned short s = (v > 0.f) ? 0x3F80 : ((v < 0.f) ? 0xBF80 : 0);
        d_w1b[n * 192 + k] = s;
        d_w1b[n * 192 + k + 64] = s;
        d_w1b[n * 192 + k + 128] = s;
    } else if (idx < 131072 + 2097152) {                 // x 3-way exact bf16 split
        int i = (int)(idx - 131072);
        int row = i >> 6, k = i & 63;
        float v = x[i];
        __nv_bfloat16 hi = __float2bfloat16(v);
        float r1 = v - __bfloat162float(hi);
        __nv_bfloat16 mid = __float2bfloat16(r1);
        float r2 = r1 - __bfloat162float(mid);
        __nv_bfloat16 lo = __float2bfloat16(r2);
        d_xp[(size_t)row * 192 + k]       = hi;
        d_xp[(size_t)row * 192 + k + 64]  = mid;
        d_xp[(size_t)row * 192 + k + 128] = lo;
    } else if (idx < 131072 + 2097152 + 65536) {         // sign(w2) s4 B-fragments
        int i = (int)(idx - 131072 - 2097152);
        int nq = i >> 10, kc = (i >> 5) & 31, lane = i & 31;
        int col = nq * 16 + (lane >> 2);
        const float* p0 = w2 + (size_t)col * 2048 + kc * 64 + (lane & 3) * 8;
        const float* p1 = p0 + 8 * 2048;
        uint4 o;
        o.x = nib8(p0); o.y = nib8(p0 + 32);
        o.z = nib8(p1); o.w = nib8(p1 + 32);
        d_w2f[i] = o;
    } else if (idx < 131072 + 2097152 + 65536 + 16384) { // sign(w3) s4 B-fragments
        int i = (int)(idx - 131072 - 2097152 - 65536);
        int nq = i >> 9, kc = (i >> 5) & 15, lane = i & 31;
        int col = nq * 16 + (lane >> 2);
        const float* p0 = w3 + (size_t)col * 1024 + kc * 64 + (lane & 3) * 8;
        const float* p1 = p0 + 8 * 1024;
        uint4 o;
        o.x = nib8(p0); o.y = nib8(p0 + 32);
        o.z = nib8(p1); o.w = nib8(p1 + 32);
        d_w3f[i] = o;
    } else if (idx < 131072 + 2097152 + 65536 + 16384 + 1024) { // w4 bitmasks
        int t = (int)(idx - 131072 - 2097152 - 65536 - 16384);
        int j = t >> 4, w = t & 15;
        unsigned p = 0, n = 0;
        #pragma unroll
        for (int i = 0; i < 32; i++) {
            float v = w4[j * 512 + w * 32 + i];
            if (v > 0.f) p |= (1u << i);
            if (v < 0.f) n |= (1u << i);
        }
        d_p4[j * 16 + w] = p;
        d_n4[j * 16 + w] = n;
    }
}

// ---------------- layer 1: bf16 mma GEMM (M=32768, N=2048, K=192) ----------------
#define L1_SMEM (49152 + 49152 + 3 * 512)
__global__ __launch_bounds__(256, 2) void l1mma_kernel(
    const float* __restrict__ b1, const float* __restrict__ g1,
    const float* __restrict__ be1, const float* __restrict__ m1,
    const float* __restrict__ v1)
{
    extern __shared__ __align__(128) char smem[];
    uint32_t sb = smem_u32(smem);
    float* ssc = (float*)(smem + 98304);
    float* sof = (float*)(smem + 98816);
    float* sbb = (float*)(smem + 99328);

    int tid = threadIdx.x, wid = tid >> 5, lane = tid & 31;
    int N0 = blockIdx.x * 128, R0 = blockIdx.y * 128;
    int warpM = (wid & 3) * 32, warpN = (wid >> 2) * 64;
    uint32_t ab = sb, bb = sb + 49152;

    const char* Ag = (const char*)(d_xp + (size_t)R0 * 192);
    const char* Wg = (const char*)(d_w1b + (size_t)N0 * 192);
    #pragma unroll
    for (int i = 0; i < 12; i++) {
        int idx = tid + i * 256;
        int r = idx / 24, sg = idx % 24;
        cp16(ab + swz384(r, sg), Ag + (size_t)r * 384 + sg * 16);
        cp16(bb + swz384(r, sg), Wg + (size_t)r * 384 + sg * 16);
    }
    asm volatile("cp.async.commit_group;");

    for (int t = tid; t < 128; t += 256) {
        int j = N0 + t;
        float sc = g1[j] / sqrtf(v1[j] + EPSBN);
        ssc[t] = sc;
        sof[t] = be1[j] - m1[j] * sc;
        sbb[t] = b1[j];
    }
    float C_[2][8][4];
    #pragma unroll
    for (int mt = 0; mt < 2; mt++)
        #pragma unroll
        for (int nt = 0; nt < 8; nt++)
            #pragma unroll
            for (int q = 0; q < 4; q++) C_[mt][nt][q] = 0.f;

    asm volatile("cp.async.wait_group 0;");
    __syncthreads();

    #pragma unroll
    for (int ks = 0; ks < 12; ks++) {
        uint32_t af[2][4];
        #pragma unroll
        for (int mt = 0; mt < 2; mt++) {
            int row = warpM + mt * 16 + (lane & 7) + ((lane >> 3) & 1) * 8;
            int sg  = ks * 2 + (lane >> 4);
            LDMX4(af[mt], ab + swz384(row, sg));
        }
        uint32_t bf[4][4];
        #pragma unroll
        for (int p = 0; p < 4; p++) {
            int row = warpN + p * 16 + (lane & 7) + (lane >> 4) * 8;
            int sg  = ks * 2 + ((lane >> 3) & 1);
            LDMX4(bf[p], bb + swz384(row, sg));
        }
        #pragma unroll
        for (int mt = 0; mt < 2; mt++)
            #pragma unroll
            for (int p = 0; p < 4; p++) {
                mma_bf16(C_[mt][2 * p],     af[mt], bf[p][0], bf[p][1]);
                mma_bf16(C_[mt][2 * p + 1], af[mt], bf[p][2], bf[p][3]);
            }
    }

    // epilogue: BN + threshold -> s4 A-fragments for L2 (warp covers 1 kc of 64)
    int kcg = (N0 + warpN) >> 6;
    #pragma unroll
    for (int mt = 0; mt < 2; mt++) {
        int rt = (R0 + warpM + mt * 16) >> 4;
        unsigned wLoA = 0, wLoB = 0, wHiA = 0, wHiB = 0;
        #pragma unroll
        for (int nt = 0; nt < 8; nt++) {
            int col = warpN + nt * 8 + (lane & 3) * 2;
            float sc0 = ssc[col],     of0 = sof[col],     bq0 = sbb[col];
            float sc1 = ssc[col + 1], of1 = sof[col + 1], bq1 = sbb[col + 1];
            unsigned t0 = (((C_[mt][nt][0] + bq0) * sc0 + of0) > 0.f) ? 1u : 0u;
            unsigned t1 = (((C_[mt][nt][1] + bq1) * sc1 + of1) > 0.f) ? 1u : 0u;
            unsigned t2 = (((C_[mt][nt][2] + bq0) * sc0 + of0) > 0.f) ? 1u : 0u;
            unsigned t3 = (((C_[mt][nt][3] + bq1) * sc1 + of1) > 0.f) ? 1u : 0u;
            unsigned blo = t0 | (t1 << 4);
            unsigned bhi = t2 | (t3 << 4);
            if (nt < 4) { wLoA |= blo << (8 * nt);       wHiA |= bhi << (8 * nt); }
            else        { wLoB |= blo << (8 * (nt - 4)); wHiB |= bhi << (8 * (nt - 4)); }
        }
        emit_afrag4(&d_a1f[((size_t)rt * 32 + kcg) * 32 + lane],
                    wLoA, wLoB, wHiA, wHiB, lane);
    }
}

// ---------------- layers 2/3: s4 mma GEMM, zero-smem fragment mainloop -----------
template<int LAYER>
__global__ __launch_bounds__(256, 2) void mmas4_kernel(
    const float* __restrict__ bbp, const float* __restrict__ g,
    const float* __restrict__ be, const float* __restrict__ m,
    const float* __restrict__ v)
{
    constexpr int KDIM = (LAYER == 2) ? 2048 : 1024;
    constexpr int NOUT = (LAYER == 2) ? 1024 : 512;
    constexpr int KC   = KDIM / 64;
    const uint4* __restrict__ Af = (LAYER == 2) ? d_a1f : d_a2f;
    const uint4* __restrict__ Wf = (LAYER == 2) ? d_w2f : d_w3f;

    __shared__ float ssc[128], sof[128], sbb[128];

    int tid = threadIdx.x, wid = tid >> 5, lane = tid & 31;
    int N0 = blockIdx.x * 128, R0 = blockIdx.y * 128;
    int warpM = (wid & 3) * 32, warpN = (wid >> 2) * 64;

    if (tid < 128) {
        int j = N0 + tid;
        float sc = g[j] / sqrtf(v[j] + EPSBN);
        ssc[tid] = sc;
        sof[tid] = be[j] - m[j] * sc;
        sbb[tid] = bbp[j];
    }
    __syncthreads();

    int rt0 = (R0 + warpM) >> 4;
    int nq0 = (N0 + warpN) >> 4;
    const uint4* Ap0 = Af + ((size_t)rt0 * KC) * 32 + lane;
    const uint4* Ap1 = Af + ((size_t)(rt0 + 1) * KC) * 32 + lane;
    const uint4* Bp0 = Wf + ((size_t)nq0 * KC) * 32 + lane;
    const uint4* Bp1 = Wf + ((size_t)(nq0 + 1) * KC) * 32 + lane;
    const uint4* Bp2 = Wf + ((size_t)(nq0 + 2) * KC) * 32 + lane;
    const uint4* Bp3 = Wf + ((size_t)(nq0 + 3) * KC) * 32 + lane;

    int C_[2][8][4];
    #pragma unroll
    for (int mt = 0; mt < 2; mt++)
        #pragma unroll
        for (int nt = 0; nt < 8; nt++)
            #pragma unroll
            for (int q = 0; q < 4; q++) C_[mt][nt][q] = 0;

    #pragma unroll 2
    for (int kc = 0; kc < KC; kc++) {
        uint4 a0 = Ap0[kc * 32];
        uint4 a1 = Ap1[kc * 32];
        uint4 b0 = Bp0[kc * 32];
        uint4 b1 = Bp1[kc * 32];
        uint4 b2 = Bp2[kc * 32];
        uint4 b3 = Bp3[kc * 32];
        const uint32_t* A0 = (const uint32_t*)&a0;
        const uint32_t* A1 = (const uint32_t*)&a1;
        mma_s4(C_[0][0], A0, b0.x, b0.y);  mma_s4(C_[0][1], A0, b0.z, b0.w);
        mma_s4(C_[0][2], A0, b1.x, b1.y);  mma_s4(C_[0][3], A0, b1.z, b1.w);
        mma_s4(C_[0][4], A0, b2.x, b2.y);  mma_s4(C_[0][5], A0, b2.z, b2.w);
        mma_s4(C_[0][6], A0, b3.x, b3.y);  mma_s4(C_[0][7], A0, b3.z, b3.w);
        mma_s4(C_[1][0], A1, b0.x, b0.y);  mma_s4(C_[1][1], A1, b0.z, b0.w);
        mma_s4(C_[1][2], A1, b1.x, b1.y);  mma_s4(C_[1][3], A1, b1.z, b1.w);
        mma_s4(C_[1][4], A1, b2.x, b2.y);  mma_s4(C_[1][5], A1, b2.z, b2.w);
        mma_s4(C_[1][6], A1, b3.x, b3.y);  mma_s4(C_[1][7], A1, b3.z, b3.w);
    }

    if (LAYER == 2) {
        // epilogue: BN + threshold -> s4 A-fragments for L3 (warp covers 1 kc)
        int kcg = (N0 + warpN) >> 6;
        #pragma unroll
        for (int mt = 0; mt < 2; mt++) {
            int rt = (R0 + warpM + mt * 16) >> 4;
            unsigned wLoA = 0, wLoB = 0, wHiA = 0, wHiB = 0;
            #pragma unroll
            for (int nt = 0; nt < 8; nt++) {
                int col = warpN + nt * 8 + (lane & 3) * 2;
                float sc0 = ssc[col],     of0 = sof[col],     bq0 = sbb[col];
                float sc1 = ssc[col + 1], of1 = sof[col + 1], bq1 = sbb[col + 1];
                unsigned t0 = ((((float)C_[mt][nt][0] + bq0) * sc0 + of0) > 0.f) ? 1u : 0u;
                unsigned t1 = ((((float)C_[mt][nt][1] + bq1) * sc1 + of1) > 0.f) ? 1u : 0u;
                unsigned t2 = ((((float)C_[mt][nt][2] + bq0) * sc0 + of0) > 0.f) ? 1u : 0u;
                unsigned t3 = ((((float)C_[mt][nt][3] + bq1) * sc1 + of1) > 0.f) ? 1u : 0u;
                unsigned blo = t0 | (t1 << 4);
                unsigned bhi = t2 | (t3 << 4);
                if (nt < 4) { wLoA |= blo << (8 * nt);       wHiA |= bhi << (8 * nt); }
                else        { wLoB |= blo << (8 * (nt - 4)); wHiB |= bhi << (8 * (nt - 4)); }
            }
            emit_afrag4(&d_a2f[((size_t)rt * 16 + kcg) * 32 + lane],
                        wLoA, wLoB, wHiA, wHiB, lane);
        }
    } else {
        // epilogue: BN + threshold -> row-major s8 (for bitify)
        #pragma unroll
        for (int mt = 0; mt < 2; mt++)
            #pragma unroll
            for (int nt = 0; nt < 8; nt++) {
                int col = warpN + nt * 8 + (lane & 3) * 2;
                int r0  = R0 + warpM + mt * 16 + (lane >> 2);
                float sc0 = ssc[col],     of0 = sof[col],     bq0 = sbb[col];
                float sc1 = ssc[col + 1], of1 = sof[col + 1], bq1 = sbb[col + 1];
                char2 u;
                u.x = ((((float)C_[mt][nt][0] + bq0) * sc0 + of0) > 0.f) ? 1 : 0;
                u.y = ((((float)C_[mt][nt][1] + bq1) * sc1 + of1) > 0.f) ? 1 : 0;
                *(char2*)&d_a3s[(size_t)r0 * NOUT + N0 + col] = u;
                u.x = ((((float)C_[mt][nt][2] + bq0) * sc0 + of0) > 0.f) ? 1 : 0;
                u.y = ((((float)C_[mt][nt][3] + bq1) * sc1 + of1) > 0.f) ? 1 : 0;
                *(char2*)&d_a3s[(size_t)(r0 + 8) * NOUT + N0 + col] = u;
            }
    }
}

// ---------------- bitify layer-3 activations -------------------------------------
__global__ __launch_bounds__(256) void bitify_kernel() {
    int idx = blockIdx.x * 256 + threadIdx.x;            // 524288 threads
    const uint4* p = (const uint4*)d_a3s + (size_t)idx * 2;
    uint4 u0 = p[0], u1 = p[1];
    unsigned vs[8] = {u0.x, u0.y, u0.z, u0.w, u1.x, u1.y, u1.z, u1.w};
    unsigned w = 0;
    #pragma unroll
    for (int i = 0; i < 8; i++)
        w |= (((vs[i] & 0x01010101u) * 0x01020408u) >> 24) << (4 * i);
    d_h3[idx] = w;
}

// ---------------- layer 4 + layer 5 + sigmoid (fused popcount) -------------------
__global__ __launch_bounds__(128) void out_kernel(
    const float* __restrict__ b4, const float* __restrict__ g4,
    const float* __restrict__ be4, const float* __restrict__ m4,
    const float* __restrict__ v4, const float* __restrict__ w5,
    const float* __restrict__ b5, float* __restrict__ out)
{
    __shared__ unsigned p4s[64 * 16], n4s[64 * 16];
    __shared__ float sc4[64], off4[64], bb4[64], w5s[64];
    int tid = threadIdx.x;
    for (int i = tid; i < 1024; i += 128) { p4s[i] = d_p4[i]; n4s[i] = d_n4[i]; }
    if (tid < 64) {
        float sc = g4[tid] / sqrtf(v4[tid] + EPSBN);
        sc4[tid] = sc;
        off4[tid] = be4[tid] - m4[tid] * sc;
        bb4[tid]  = b4[tid];
        w5s[tid]  = w5[tid];
    }
    __syncthreads();

    int row = blockIdx.x * 128 + tid;
    unsigned h[16];
    #pragma unroll
    for (int q = 0; q < 4; q++) {
        uint4 t = *(const uint4*)&d_h3[(size_t)row * 16 + q * 4];
        h[q * 4] = t.x; h[q * 4 + 1] = t.y; h[q * 4 + 2] = t.z; h[q * 4 + 3] = t.w;
    }

    float z = b5[0];
    #pragma unroll 4
    for (int j = 0; j < 64; j++) {
        int a = 0, bn = 0;
        #pragma unroll
        for (int k = 0; k < 16; k++) {
            a  += __popc(h[k] & p4s[j * 16 + k]);
            bn += __popc(h[k] & n4s[j * 16 + k]);
        }
        float t = ((float)(a - bn) + bb4[j]) * sc4[j] + off4[j];
        if (t > 0.f) z += w5s[j];
    }
    out[row] = 1.f / (1.f + expf(-z));
}

// ---------------- launch ---------------------------------------------------------
extern "C" void kernel_launch(void* const* d_in, const int* in_sizes, int n_in,
                              void* d_out, int out_size) {
    const float* x   = (const float*)d_in[0];
    const float* w1  = (const float*)d_in[1];
    const float* b1  = (const float*)d_in[2];
    const float* w2  = (const float*)d_in[3];
    const float* b2  = (const float*)d_in[4];
    const float* w3  = (const float*)d_in[5];
    const float* b3  = (const float*)d_in[6];
    const float* w4  = (const float*)d_in[7];
    const float* b4  = (const float*)d_in[8];
    const float* w5  = (const float*)d_in[9];
    const float* b5  = (const float*)d_in[10];
    const float* g1  = (const float*)d_in[11];
    const float* be1 = (const float*)d_in[12];
    const float* m1  = (const float*)d_in[13];
    const float* v1  = (const float*)d_in[14];
    const float* g2  = (const float*)d_in[15];
    const float* be2 = (const float*)d_in[16];
    const float* m2  = (const float*)d_in[17];
    const float* v2  = (const float*)d_in[18];
    const float* g3  = (const float*)d_in[19];
    const float* be3 = (const float*)d_in[20];
    const float* m3  = (const float*)d_in[21];
    const float* v3  = (const float*)d_in[22];
    const float* g4  = (const float*)d_in[23];
    const float* be4 = (const float*)d_in[24];
    const float* m4  = (const float*)d_in[25];
    const float* v4  = (const float*)d_in[26];
    float* out = (float*)d_out;

    cudaFuncSetAttribute(l1mma_kernel, cudaFuncAttributeMaxDynamicSharedMemorySize, L1_SMEM);

    pack_all<<<9028, 256>>>(x, w1, w2, w3, w4);
    l1mma_kernel<<<dim3(16, 256), 256, L1_SMEM>>>(b1, g1, be1, m1, v1);
    mmas4_kernel<2><<<dim3(8, 256), 256>>>(b2, g2, be2, m2, v2);
    mmas4_kernel<3><<<dim3(4, 256), 256>>>(b3, g3, be3, m3, v3);
    bitify_kernel<<<2048, 256>>>();
    out_kernel<<<256, 128>>>(b4, g4, be4, m4, v4, w5, b5, out);
}

// round 16
// speedup vs baseline: 7.5446x; 7.5446x over previous
#include <cuda_runtime.h>
#include <cuda_bf16.h>
#include <math.h>
#include <stdint.h>

// Linear_bin: binarized 5-layer MLP, B=32768, 64->2048->1024->512->64->1.
// L1: bf16 mma GEMM (exact 3-way split of x), epilogue emits A-fragments for L2.
// L2, L3: s8 mma.m16n8k32 GEMMs, zero-smem fragment mainloop (R7 structure);
//         streamed A-fragments loaded with ld.global.cg (L1 bypass) so the
//         L2-hot B-fragments keep their L1 residency.
// L4+L5+sigmoid: fused popcount kernel.

#define BATCH 32768
#define EPSBN 1e-5f

// ---------------- scratch (static device globals; no allocation) ----------------
__device__ __align__(16) __nv_bfloat16 d_xp[BATCH * 192];     // x split: hi|mid|lo
__device__ __align__(16) unsigned short d_w1b[2048 * 192];    // sign(w1) bf16, 3x replicated
__device__ __align__(16) uint4 d_w2f[(1024 / 16) * 64 * 32];  // sign(w2) B-fragments
__device__ __align__(16) uint4 d_w3f[(512 / 16) * 32 * 32];   // sign(w3) B-fragments
__device__ __align__(16) uint4 d_a1f[2048 * 64 * 32];         // L1 acts as L2 A-fragments (64MB)
__device__ __align__(16) uint4 d_a2f[2048 * 32 * 32];         // L2 acts as L3 A-fragments (32MB)
__device__ unsigned d_p4[64 * 16];
__device__ unsigned d_n4[64 * 16];
__device__ __align__(16) char  d_a3s[BATCH * 512];            // L3 acts {0,1} row-major
__device__ __align__(16) unsigned d_h3[BATCH * 16];           // L3 bits

// ---------------- helpers --------------------------------------------------------
__device__ __forceinline__ uint32_t smem_u32(const void* p) {
    uint32_t a;
    asm("{ .reg .u64 t; cvta.to.shared.u64 t, %1; cvt.u32.u64 %0, t; }" : "=r"(a) : "l"(p));
    return a;
}
#define LDMX4(r, a) \
    asm volatile("ldmatrix.sync.aligned.m8n8.x4.shared.b16 {%0,%1,%2,%3}, [%4];" \
        : "=r"((r)[0]), "=r"((r)[1]), "=r"((r)[2]), "=r"((r)[3]) : "r"(a))

// streamed load, bypass L1 (cache-global only)
__device__ __forceinline__ uint4 ldcg16(const uint4* p) {
    uint4 v;
    asm volatile("ld.global.cg.v4.u32 {%0,%1,%2,%3}, [%4];"
        : "=r"(v.x), "=r"(v.y), "=r"(v.z), "=r"(v.w) : "l"(p));
    return v;
}

__device__ __forceinline__ void mma_s8(int* c, const uint32_t* a, uint32_t b0, uint32_t b1) {
    asm volatile(
        "mma.sync.aligned.m16n8k32.row.col.s32.s8.s8.s32 "
        "{%0,%1,%2,%3}, {%4,%5,%6,%7}, {%8,%9}, {%0,%1,%2,%3};"
        : "+r"(c[0]), "+r"(c[1]), "+r"(c[2]), "+r"(c[3])
        : "r"(a[0]), "r"(a[1]), "r"(a[2]), "r"(a[3]), "r"(b0), "r"(b1));
}
__device__ __forceinline__ void mma_bf16(float* c, const uint32_t* a, uint32_t b0, uint32_t b1) {
    asm volatile(
        "mma.sync.aligned.m16n8k16.row.col.f32.bf16.bf16.f32 "
        "{%0,%1,%2,%3}, {%4,%5,%6,%7}, {%8,%9}, {%0,%1,%2,%3};"
        : "+f"(c[0]), "+f"(c[1]), "+f"(c[2]), "+f"(c[3])
        : "r"(a[0]), "r"(a[1]), "r"(a[2]), "r"(a[3]), "r"(b0), "r"(b1));
}
__device__ __forceinline__ void cp16(uint32_t dst, const void* src) {
    asm volatile("cp.async.cg.shared.global [%0], [%1], 16;" :: "r"(dst), "l"(src));
}
// 384-byte rows (K=192 bf16): swizzle within each 128B third
__device__ __forceinline__ uint32_t swz384(int r, int s) {
    return (uint32_t)(r * 384 + (((s & 24) | ((s ^ r) & 7)) << 4));
}
__device__ __forceinline__ unsigned sgn4(const float* p) {
    unsigned r = 0;
    #pragma unroll
    for (int j = 0; j < 4; j++) {
        float v = p[j];
        int s = (v > 0.f) ? 1 : ((v < 0.f) ? -1 : 0);
        r |= ((unsigned)(s & 0xff)) << (8 * j);
    }
    return r;
}

// ---- fragment-emission epilogue core ------------------------------------------
__device__ __forceinline__ void emit_afrag(
    uint4* dst, unsigned lo0, unsigned lo1, unsigned lo2, unsigned lo3,
    unsigned hi0, unsigned hi1, unsigned hi2, unsigned hi3, int lane)
{
    unsigned ploA = lo0 | (lo1 << 16), ploB = lo2 | (lo3 << 16);
    unsigned phiA = hi0 | (hi1 << 16), phiB = hi2 | (hi3 << 16);
    int s0 = 4 * (lane >> 2) + 2 * (lane & 1);
    unsigned selm = (lane & 2) ? 0x7632u : 0x5410u;
    uint4 o;
    o.x = __byte_perm(__shfl_sync(0xffffffffu, ploA, s0),
                      __shfl_sync(0xffffffffu, ploA, s0 + 1), selm);
    o.y = __byte_perm(__shfl_sync(0xffffffffu, phiA, s0),
                      __shfl_sync(0xffffffffu, phiA, s0 + 1), selm);
    o.z = __byte_perm(__shfl_sync(0xffffffffu, ploB, s0),
                      __shfl_sync(0xffffffffu, ploB, s0 + 1), selm);
    o.w = __byte_perm(__shfl_sync(0xffffffffu, phiB, s0),
                      __shfl_sync(0xffffffffu, phiB, s0 + 1), selm);
    *dst = o;
}

// ---------------- weight preprocessing + x split ---------------------------------
// threads: w1b 131072 | xp 2097152 | w2f 131072 | w3f 32768 | w4 1024 = 2393088
__global__ void pack_all(const float* __restrict__ x,  const float* __restrict__ w1,
                         const float* __restrict__ w2, const float* __restrict__ w3,
                         const float* __restrict__ w4) {
    long idx = (long)blockIdx.x * 256 + threadIdx.x;
    if (idx < 131072) {                                  // sign(w1) bf16, replicated x3
        int n = (int)idx >> 6, k = (int)idx & 63;
        float v = w1[n * 64 + k];
        unsigned short s = (v > 0.f) ? 0x3F80 : ((v < 0.f) ? 0xBF80 : 0);
        d_w1b[n * 192 + k] = s;
        d_w1b[n * 192 + k + 64] = s;
        d_w1b[n * 192 + k + 128] = s;
    } else if (idx < 131072 + 2097152) {                 // x 3-way exact bf16 split
        int i = (int)(idx - 131072);
        int row = i >> 6, k = i & 63;
        float v = x[i];
        __nv_bfloat16 hi = __float2bfloat16(v);
        float r1 = v - __bfloat162float(hi);
        __nv_bfloat16 mid = __float2bfloat16(r1);
        float r2 = r1 - __bfloat162float(mid);
        __nv_bfloat16 lo = __float2bfloat16(r2);
        d_xp[(size_t)row * 192 + k]       = hi;
        d_xp[(size_t)row * 192 + k + 64]  = mid;
        d_xp[(size_t)row * 192 + k + 128] = lo;
    } else if (idx < 131072 + 2097152 + 131072) {        // sign(w2) B-fragments
        int i = (int)(idx - 131072 - 2097152);
        int nq = i >> 11, kc = (i >> 5) & 63, lane = i & 31;
        int col = nq * 16 + (lane >> 2);
        int kb  = kc * 32 + (lane & 3) * 4;
        const float* p0 = w2 + (size_t)col * 2048 + kb;
        const float* p1 = p0 + 8 * 2048;
        uint4 o;
        o.x = sgn4(p0); o.y = sgn4(p0 + 16);
        o.z = sgn4(p1); o.w = sgn4(p1 + 16);
        d_w2f[i] = o;
    } else if (idx < 131072 + 2097152 + 131072 + 32768) { // sign(w3) B-fragments
        int i = (int)(idx - 131072 - 2097152 - 131072);
        int nq = i >> 10, kc = (i >> 5) & 31, lane = i & 31;
        int col = nq * 16 + (lane >> 2);
        int kb  = kc * 32 + (lane & 3) * 4;
        const float* p0 = w3 + (size_t)col * 1024 + kb;
        const float* p1 = p0 + 8 * 1024;
        uint4 o;
        o.x = sgn4(p0); o.y = sgn4(p0 + 16);
        o.z = sgn4(p1); o.w = sgn4(p1 + 16);
        d_w3f[i] = o;
    } else if (idx < 131072 + 2097152 + 131072 + 32768 + 1024) { // w4 bitmasks
        int t = (int)(idx - 131072 - 2097152 - 131072 - 32768);
        int j = t >> 4, w = t & 15;
        unsigned p = 0, n = 0;
        #pragma unroll
        for (int i = 0; i < 32; i++) {
            float v = w4[j * 512 + w * 32 + i];
            if (v > 0.f) p |= (1u << i);
            if (v < 0.f) n |= (1u << i);
        }
        d_p4[j * 16 + w] = p;
        d_n4[j * 16 + w] = n;
    }
}

// ---------------- layer 1: bf16 mma GEMM (M=32768, N=2048, K=192) ----------------
#define L1_SMEM (49152 + 49152 + 3 * 512)
__global__ __launch_bounds__(256, 2) void l1mma_kernel(
    const float* __restrict__ b1, const float* __restrict__ g1,
    const float* __restrict__ be1, const float* __restrict__ m1,
    const float* __restrict__ v1)
{
    extern __shared__ __align__(128) char smem[];
    uint32_t sb = smem_u32(smem);
    float* ssc = (float*)(smem + 98304);
    float* sof = (float*)(smem + 98816);
    float* sbb = (float*)(smem + 99328);

    int tid = threadIdx.x, wid = tid >> 5, lane = tid & 31;
    int N0 = blockIdx.x * 128, R0 = blockIdx.y * 128;
    int warpM = (wid & 3) * 32, warpN = (wid >> 2) * 64;
    uint32_t ab = sb, bb = sb + 49152;

    const char* Ag = (const char*)(d_xp + (size_t)R0 * 192);
    const char* Wg = (const char*)(d_w1b + (size_t)N0 * 192);
    #pragma unroll
    for (int i = 0; i < 12; i++) {
        int idx = tid + i * 256;
        int r = idx / 24, sg = idx % 24;
        cp16(ab + swz384(r, sg), Ag + (size_t)r * 384 + sg * 16);
        cp16(bb + swz384(r, sg), Wg + (size_t)r * 384 + sg * 16);
    }
    asm volatile("cp.async.commit_group;");

    for (int t = tid; t < 128; t += 256) {
        int j = N0 + t;
        float sc = g1[j] / sqrtf(v1[j] + EPSBN);
        ssc[t] = sc;
        sof[t] = be1[j] - m1[j] * sc;
        sbb[t] = b1[j];
    }
    float C_[2][8][4];
    #pragma unroll
    for (int mt = 0; mt < 2; mt++)
        #pragma unroll
        for (int nt = 0; nt < 8; nt++)
            #pragma unroll
            for (int q = 0; q < 4; q++) C_[mt][nt][q] = 0.f;

    asm volatile("cp.async.wait_group 0;");
    __syncthreads();

    #pragma unroll
    for (int ks = 0; ks < 12; ks++) {
        uint32_t af[2][4];
        #pragma unroll
        for (int mt = 0; mt < 2; mt++) {
            int row = warpM + mt * 16 + (lane & 7) + ((lane >> 3) & 1) * 8;
            int sg  = ks * 2 + (lane >> 4);
            LDMX4(af[mt], ab + swz384(row, sg));
        }
        uint32_t bf[4][4];
        #pragma unroll
        for (int p = 0; p < 4; p++) {
            int row = warpN + p * 16 + (lane & 7) + (lane >> 4) * 8;
            int sg  = ks * 2 + ((lane >> 3) & 1);
            LDMX4(bf[p], bb + swz384(row, sg));
        }
        #pragma unroll
        for (int mt = 0; mt < 2; mt++)
            #pragma unroll
            for (int p = 0; p < 4; p++) {
                mma_bf16(C_[mt][2 * p],     af[mt], bf[p][0], bf[p][1]);
                mma_bf16(C_[mt][2 * p + 1], af[mt], bf[p][2], bf[p][3]);
            }
    }

    // epilogue: BN + threshold -> L2 A-fragments (KC = 64)
    #pragma unroll
    for (int mt = 0; mt < 2; mt++) {
        int rt = (R0 + warpM + mt * 16) >> 4;
        #pragma unroll
        for (int kc2 = 0; kc2 < 2; kc2++) {
            unsigned lo[4], hi[4];
            #pragma unroll
            for (int i = 0; i < 4; i++) {
                int nt = kc2 * 4 + i;
                int col = warpN + nt * 8 + (lane & 3) * 2;
                float sc0 = ssc[col],     of0 = sof[col],     bq0 = sbb[col];
                float sc1 = ssc[col + 1], of1 = sof[col + 1], bq1 = sbb[col + 1];
                unsigned b0 = (((C_[mt][nt][0] + bq0) * sc0 + of0) > 0.f) ? 1u : 0u;
                unsigned b1 = (((C_[mt][nt][1] + bq1) * sc1 + of1) > 0.f) ? 1u : 0u;
                unsigned b2 = (((C_[mt][nt][2] + bq0) * sc0 + of0) > 0.f) ? 1u : 0u;
                unsigned b3 = (((C_[mt][nt][3] + bq1) * sc1 + of1) > 0.f) ? 1u : 0u;
                lo[i] = b0 | (b1 << 8);
                hi[i] = b2 | (b3 << 8);
            }
            int kcg = ((N0 + warpN) >> 5) + kc2;
            emit_afrag(&d_a1f[((size_t)rt * 64 + kcg) * 32 + lane],
                       lo[0], lo[1], lo[2], lo[3], hi[0], hi[1], hi[2], hi[3], lane);
        }
    }
}

// ---------------- layers 2/3: s8 mma GEMM, zero-smem fragment mainloop -----------
// A (streamed, no reuse) via ld.global.cg (L1 bypass); B (hot) default-cached.
template<int LAYER>
__global__ __launch_bounds__(256, 2) void mmas8_kernel(
    const float* __restrict__ bbp, const float* __restrict__ g,
    const float* __restrict__ be, const float* __restrict__ m,
    const float* __restrict__ v)
{
    constexpr int KDIM = (LAYER == 2) ? 2048 : 1024;
    constexpr int NOUT = (LAYER == 2) ? 1024 : 512;
    constexpr int KC   = KDIM / 32;
    const uint4* __restrict__ Af = (LAYER == 2) ? d_a1f : d_a2f;
    const uint4* __restrict__ Wf = (LAYER == 2) ? d_w2f : d_w3f;

    __shared__ float ssc[128], sof[128], sbb[128];

    int tid = threadIdx.x, wid = tid >> 5, lane = tid & 31;
    int N0 = blockIdx.x * 128, R0 = blockIdx.y * 128;
    int warpM = (wid & 3) * 32, warpN = (wid >> 2) * 64;

    if (tid < 128) {
        int j = N0 + tid;
        float sc = g[j] / sqrtf(v[j] + EPSBN);
        ssc[tid] = sc;
        sof[tid] = be[j] - m[j] * sc;
        sbb[tid] = bbp[j];
    }
    __syncthreads();

    int rt0 = (R0 + warpM) >> 4;
    int nq0 = (N0 + warpN) >> 4;
    const uint4* Ap0 = Af + ((size_t)rt0 * KC) * 32 + lane;
    const uint4* Ap1 = Af + ((size_t)(rt0 + 1) * KC) * 32 + lane;
    const uint4* Bp0 = Wf + ((size_t)nq0 * KC) * 32 + lane;
    const uint4* Bp1 = Wf + ((size_t)(nq0 + 1) * KC) * 32 + lane;
    const uint4* Bp2 = Wf + ((size_t)(nq0 + 2) * KC) * 32 + lane;
    const uint4* Bp3 = Wf + ((size_t)(nq0 + 3) * KC) * 32 + lane;

    int C_[2][8][4];
    #pragma unroll
    for (int mt = 0; mt < 2; mt++)
        #pragma unroll
        for (int nt = 0; nt < 8; nt++)
            #pragma unroll
            for (int q = 0; q < 4; q++) C_[mt][nt][q] = 0;

    #pragma unroll 2
    for (int kc = 0; kc < KC; kc++) {
        uint4 a0 = ldcg16(Ap0 + kc * 32);
        uint4 a1 = ldcg16(Ap1 + kc * 32);
        uint4 b0 = Bp0[kc * 32];
        uint4 b1 = Bp1[kc * 32];
        uint4 b2 = Bp2[kc * 32];
        uint4 b3 = Bp3[kc * 32];
        const uint32_t* A0 = (const uint32_t*)&a0;
        const uint32_t* A1 = (const uint32_t*)&a1;
        mma_s8(C_[0][0], A0, b0.x, b0.y);  mma_s8(C_[0][1], A0, b0.z, b0.w);
        mma_s8(C_[0][2], A0, b1.x, b1.y);  mma_s8(C_[0][3], A0, b1.z, b1.w);
        mma_s8(C_[0][4], A0, b2.x, b2.y);  mma_s8(C_[0][5], A0, b2.z, b2.w);
        mma_s8(C_[0][6], A0, b3.x, b3.y);  mma_s8(C_[0][7], A0, b3.z, b3.w);
        mma_s8(C_[1][0], A1, b0.x, b0.y);  mma_s8(C_[1][1], A1, b0.z, b0.w);
        mma_s8(C_[1][2], A1, b1.x, b1.y);  mma_s8(C_[1][3], A1, b1.z, b1.w);
        mma_s8(C_[1][4], A1, b2.x, b2.y);  mma_s8(C_[1][5], A1, b2.z, b2.w);
        mma_s8(C_[1][6], A1, b3.x, b3.y);  mma_s8(C_[1][7], A1, b3.z, b3.w);
    }

    if (LAYER == 2) {
        // epilogue: BN + threshold -> L3 A-fragments (KC_out = 32)
        #pragma unroll
        for (int mt = 0; mt < 2; mt++) {
            int rt = (R0 + warpM + mt * 16) >> 4;
            #pragma unroll
            for (int kc2 = 0; kc2 < 2; kc2++) {
                unsigned lo[4], hi[4];
                #pragma unroll
                for (int i = 0; i < 4; i++) {
                    int nt = kc2 * 4 + i;
                    int col = warpN + nt * 8 + (lane & 3) * 2;
                    float sc0 = ssc[col],     of0 = sof[col],     bq0 = sbb[col];
                    float sc1 = ssc[col + 1], of1 = sof[col + 1], bq1 = sbb[col + 1];
                    unsigned b0 = ((((float)C_[mt][nt][0] + bq0) * sc0 + of0) > 0.f) ? 1u : 0u;
                    unsigned b1 = ((((float)C_[mt][nt][1] + bq1) * sc1 + of1) > 0.f) ? 1u : 0u;
                    unsigned b2 = ((((float)C_[mt][nt][2] + bq0) * sc0 + of0) > 0.f) ? 1u : 0u;
                    unsigned b3 = ((((float)C_[mt][nt][3] + bq1) * sc1 + of1) > 0.f) ? 1u : 0u;
                    lo[i] = b0 | (b1 << 8);
                    hi[i] = b2 | (b3 << 8);
                }
                int kcg = ((N0 + warpN) >> 5) + kc2;
                emit_afrag(&d_a2f[((size_t)rt * 32 + kcg) * 32 + lane],
                           lo[0], lo[1], lo[2], lo[3], hi[0], hi[1], hi[2], hi[3], lane);
            }
        }
    } else {
        // epilogue: BN + threshold -> row-major s8 (for bitify)
        #pragma unroll
        for (int mt = 0; mt < 2; mt++)
            #pragma unroll
            for (int nt = 0; nt < 8; nt++) {
                int col = warpN + nt * 8 + (lane & 3) * 2;
                int r0  = R0 + warpM + mt * 16 + (lane >> 2);
                float sc0 = ssc[col],     of0 = sof[col],     bq0 = sbb[col];
                float sc1 = ssc[col + 1], of1 = sof[col + 1], bq1 = sbb[col + 1];
                char2 u;
                u.x = ((((float)C_[mt][nt][0] + bq0) * sc0 + of0) > 0.f) ? 1 : 0;
                u.y = ((((float)C_[mt][nt][1] + bq1) * sc1 + of1) > 0.f) ? 1 : 0;
                *(char2*)&d_a3s[(size_t)r0 * NOUT + N0 + col] = u;
                u.x = ((((float)C_[mt][nt][2] + bq0) * sc0 + of0) > 0.f) ? 1 : 0;
                u.y = ((((float)C_[mt][nt][3] + bq1) * sc1 + of1) > 0.f) ? 1 : 0;
                *(char2*)&d_a3s[(size_t)(r0 + 8) * NOUT + N0 + col] = u;
            }
    }
}

// ---------------- bitify layer-3 activations -------------------------------------
__global__ __launch_bounds__(256) void bitify_kernel() {
    int idx = blockIdx.x * 256 + threadIdx.x;            // 524288 threads
    const uint4* p = (const uint4*)d_a3s + (size_t)idx * 2;
    uint4 u0 = p[0], u1 = p[1];
    unsigned vs[8] = {u0.x, u0.y, u0.z, u0.w, u1.x, u1.y, u1.z, u1.w};
    unsigned w = 0;
    #pragma unroll
    for (int i = 0; i < 8; i++)
        w |= (((vs[i] & 0x01010101u) * 0x01020408u) >> 24) << (4 * i);
    d_h3[idx] = w;
}

// ---------------- layer 4 + layer 5 + sigmoid (fused popcount) -------------------
__global__ __launch_bounds__(128) void out_kernel(
    const float* __restrict__ b4, const float* __restrict__ g4,
    const float* __restrict__ be4, const float* __restrict__ m4,
    const float* __restrict__ v4, const float* __restrict__ w5,
    const float* __restrict__ b5, float* __restrict__ out)
{
    __shared__ unsigned p4s[64 * 16], n4s[64 * 16];
    __shared__ float sc4[64], off4[64], bb4[64], w5s[64];
    int tid = threadIdx.x;
    for (int i = tid; i < 1024; i += 128) { p4s[i] = d_p4[i]; n4s[i] = d_n4[i]; }
    if (tid < 64) {
        float sc = g4[tid] / sqrtf(v4[tid] + EPSBN);
        sc4[tid] = sc;
        off4[tid] = be4[tid] - m4[tid] * sc;
        bb4[tid]  = b4[tid];
        w5s[tid]  = w5[tid];
    }
    __syncthreads();

    int row = blockIdx.x * 128 + tid;
    unsigned h[16];
    #pragma unroll
    for (int q = 0; q < 4; q++) {
        uint4 t = *(const uint4*)&d_h3[(size_t)row * 16 + q * 4];
        h[q * 4] = t.x; h[q * 4 + 1] = t.y; h[q * 4 + 2] = t.z; h[q * 4 + 3] = t.w;
    }

    float z = b5[0];
    #pragma unroll 4
    for (int j = 0; j < 64; j++) {
        int a = 0, bn = 0;
        #pragma unroll
        for (int k = 0; k < 16; k++) {
            a  += __popc(h[k] & p4s[j * 16 + k]);
            bn += __popc(h[k] & n4s[j * 16 + k]);
        }
        float t = ((float)(a - bn) + bb4[j]) * sc4[j] + off4[j];
        if (t > 0.f) z += w5s[j];
    }
    out[row] = 1.f / (1.f + expf(-z));
}

// ---------------- launch ---------------------------------------------------------
extern "C" void kernel_launch(void* const* d_in, const int* in_sizes, int n_in,
                              void* d_out, int out_size) {
    const float* x   = (const float*)d_in[0];
    const float* w1  = (const float*)d_in[1];
    const float* b1  = (const float*)d_in[2];
    const float* w2  = (const float*)d_in[3];
    const float* b2  = (const float*)d_in[4];
    const float* w3  = (const float*)d_in[5];
    const float* b3  = (const float*)d_in[6];
    const float* w4  = (const float*)d_in[7];
    const float* b4  = (const float*)d_in[8];
    const float* w5  = (const float*)d_in[9];
    const float* b5  = (const float*)d_in[10];
    const float* g1  = (const float*)d_in[11];
    const float* be1 = (const float*)d_in[12];
    const float* m1  = (const float*)d_in[13];
    const float* v1  = (const float*)d_in[14];
    const float* g2  = (const float*)d_in[15];
    const float* be2 = (const float*)d_in[16];
    const float* m2  = (const float*)d_in[17];
    const float* v2  = (const float*)d_in[18];
    const float* g3  = (const float*)d_in[19];
    const float* be3 = (const float*)d_in[20];
    const float* m3  = (const float*)d_in[21];
    const float* v3  = (const float*)d_in[22];
    const float* g4  = (const float*)d_in[23];
    const float* be4 = (const float*)d_in[24];
    const float* m4  = (const float*)d_in[25];
    const float* v4  = (const float*)d_in[26];
    float* out = (float*)d_out;

    cudaFuncSetAttribute(l1mma_kernel, cudaFuncAttributeMaxDynamicSharedMemorySize, L1_SMEM);

    pack_all<<<9348, 256>>>(x, w1, w2, w3, w4);
    l1mma_kernel<<<dim3(16, 256), 256, L1_SMEM>>>(b1, g1, be1, m1, v1);
    mmas8_kernel<2><<<dim3(8, 256), 256>>>(b2, g2, be2, m2, v2);
    mmas8_kernel<3><<<dim3(4, 256), 256>>>(b3, g3, be3, m3, v3);
    bitify_kernel<<<2048, 256>>>();
    out_kernel<<<256, 128>>>(b4, g4, be4, m4, v4, w5, b5, out);
}

// round 17
// speedup vs baseline: 9.2595x; 1.2273x over previous
#include <cuda_runtime.h>
#include <cuda_bf16.h>
#include <math.h>
#include <stdint.h>

// Linear_bin: binarized 5-layer MLP, B=32768, 64->2048->1024->512->64->1.
// L1: bf16 mma GEMM (exact 3-way split of x), epilogue emits A-fragments for L2.
// L2, L3: s8 mma.m16n8k32 GEMMs, zero-smem fragment mainloop (R7 structure)
//         with per-warp ROTATED K order to decorrelate cross-warp LDG bursts
//         (integer accumulation is order-independent -> bit-identical).
// L4+L5+sigmoid: fused popcount kernel.

#define BATCH 32768
#define EPSBN 1e-5f

// ---------------- scratch (static device globals; no allocation) ----------------
__device__ __align__(16) __nv_bfloat16 d_xp[BATCH * 192];     // x split: hi|mid|lo
__device__ __align__(16) unsigned short d_w1b[2048 * 192];    // sign(w1) bf16, 3x replicated
__device__ __align__(16) uint4 d_w2f[(1024 / 16) * 64 * 32];  // sign(w2) B-fragments
__device__ __align__(16) uint4 d_w3f[(512 / 16) * 32 * 32];   // sign(w3) B-fragments
__device__ __align__(16) uint4 d_a1f[2048 * 64 * 32];         // L1 acts as L2 A-fragments (64MB)
__device__ __align__(16) uint4 d_a2f[2048 * 32 * 32];         // L2 acts as L3 A-fragments (32MB)
__device__ unsigned d_p4[64 * 16];
__device__ unsigned d_n4[64 * 16];
__device__ __align__(16) char  d_a3s[BATCH * 512];            // L3 acts {0,1} row-major
__device__ __align__(16) unsigned d_h3[BATCH * 16];           // L3 bits

// ---------------- helpers --------------------------------------------------------
__device__ __forceinline__ uint32_t smem_u32(const void* p) {
    uint32_t a;
    asm("{ .reg .u64 t; cvta.to.shared.u64 t, %1; cvt.u32.u64 %0, t; }" : "=r"(a) : "l"(p));
    return a;
}
#define LDMX4(r, a) \
    asm volatile("ldmatrix.sync.aligned.m8n8.x4.shared.b16 {%0,%1,%2,%3}, [%4];" \
        : "=r"((r)[0]), "=r"((r)[1]), "=r"((r)[2]), "=r"((r)[3]) : "r"(a))

__device__ __forceinline__ void mma_s8(int* c, const uint32_t* a, uint32_t b0, uint32_t b1) {
    asm volatile(
        "mma.sync.aligned.m16n8k32.row.col.s32.s8.s8.s32 "
        "{%0,%1,%2,%3}, {%4,%5,%6,%7}, {%8,%9}, {%0,%1,%2,%3};"
        : "+r"(c[0]), "+r"(c[1]), "+r"(c[2]), "+r"(c[3])
        : "r"(a[0]), "r"(a[1]), "r"(a[2]), "r"(a[3]), "r"(b0), "r"(b1));
}
__device__ __forceinline__ void mma_bf16(float* c, const uint32_t* a, uint32_t b0, uint32_t b1) {
    asm volatile(
        "mma.sync.aligned.m16n8k16.row.col.f32.bf16.bf16.f32 "
        "{%0,%1,%2,%3}, {%4,%5,%6,%7}, {%8,%9}, {%0,%1,%2,%3};"
        : "+f"(c[0]), "+f"(c[1]), "+f"(c[2]), "+f"(c[3])
        : "r"(a[0]), "r"(a[1]), "r"(a[2]), "r"(a[3]), "r"(b0), "r"(b1));
}
__device__ __forceinline__ void cp16(uint32_t dst, const void* src) {
    asm volatile("cp.async.cg.shared.global [%0], [%1], 16;" :: "r"(dst), "l"(src));
}
// 384-byte rows (K=192 bf16): swizzle within each 128B third
__device__ __forceinline__ uint32_t swz384(int r, int s) {
    return (uint32_t)(r * 384 + (((s & 24) | ((s ^ r) & 7)) << 4));
}
__device__ __forceinline__ unsigned sgn4(const float* p) {
    unsigned r = 0;
    #pragma unroll
    for (int j = 0; j < 4; j++) {
        float v = p[j];
        int s = (v > 0.f) ? 1 : ((v < 0.f) ? -1 : 0);
        r |= ((unsigned)(s & 0xff)) << (8 * j);
    }
    return r;
}

// ---- fragment-emission epilogue core ------------------------------------------
__device__ __forceinline__ void emit_afrag(
    uint4* dst, unsigned lo0, unsigned lo1, unsigned lo2, unsigned lo3,
    unsigned hi0, unsigned hi1, unsigned hi2, unsigned hi3, int lane)
{
    unsigned ploA = lo0 | (lo1 << 16), ploB = lo2 | (lo3 << 16);
    unsigned phiA = hi0 | (hi1 << 16), phiB = hi2 | (hi3 << 16);
    int s0 = 4 * (lane >> 2) + 2 * (lane & 1);
    unsigned selm = (lane & 2) ? 0x7632u : 0x5410u;
    uint4 o;
    o.x = __byte_perm(__shfl_sync(0xffffffffu, ploA, s0),
                      __shfl_sync(0xffffffffu, ploA, s0 + 1), selm);
    o.y = __byte_perm(__shfl_sync(0xffffffffu, phiA, s0),
                      __shfl_sync(0xffffffffu, phiA, s0 + 1), selm);
    o.z = __byte_perm(__shfl_sync(0xffffffffu, ploB, s0),
                      __shfl_sync(0xffffffffu, ploB, s0 + 1), selm);
    o.w = __byte_perm(__shfl_sync(0xffffffffu, phiB, s0),
                      __shfl_sync(0xffffffffu, phiB, s0 + 1), selm);
    *dst = o;
}

// ---------------- weight preprocessing + x split ---------------------------------
// threads: w1b 131072 | xp 2097152 | w2f 131072 | w3f 32768 | w4 1024 = 2393088
__global__ void pack_all(const float* __restrict__ x,  const float* __restrict__ w1,
                         const float* __restrict__ w2, const float* __restrict__ w3,
                         const float* __restrict__ w4) {
    long idx = (long)blockIdx.x * 256 + threadIdx.x;
    if (idx < 131072) {                                  // sign(w1) bf16, replicated x3
        int n = (int)idx >> 6, k = (int)idx & 63;
        float v = w1[n * 64 + k];
        unsigned short s = (v > 0.f) ? 0x3F80 : ((v < 0.f) ? 0xBF80 : 0);
        d_w1b[n * 192 + k] = s;
        d_w1b[n * 192 + k + 64] = s;
        d_w1b[n * 192 + k + 128] = s;
    } else if (idx < 131072 + 2097152) {                 // x 3-way exact bf16 split
        int i = (int)(idx - 131072);
        int row = i >> 6, k = i & 63;
        float v = x[i];
        __nv_bfloat16 hi = __float2bfloat16(v);
        float r1 = v - __bfloat162float(hi);
        __nv_bfloat16 mid = __float2bfloat16(r1);
        float r2 = r1 - __bfloat162float(mid);
        __nv_bfloat16 lo = __float2bfloat16(r2);
        d_xp[(size_t)row * 192 + k]       = hi;
        d_xp[(size_t)row * 192 + k + 64]  = mid;
        d_xp[(size_t)row * 192 + k + 128] = lo;
    } else if (idx < 131072 + 2097152 + 131072) {        // sign(w2) B-fragments
        int i = (int)(idx - 131072 - 2097152);
        int nq = i >> 11, kc = (i >> 5) & 63, lane = i & 31;
        int col = nq * 16 + (lane >> 2);
        int kb  = kc * 32 + (lane & 3) * 4;
        const float* p0 = w2 + (size_t)col * 2048 + kb;
        const float* p1 = p0 + 8 * 2048;
        uint4 o;
        o.x = sgn4(p0); o.y = sgn4(p0 + 16);
        o.z = sgn4(p1); o.w = sgn4(p1 + 16);
        d_w2f[i] = o;
    } else if (idx < 131072 + 2097152 + 131072 + 32768) { // sign(w3) B-fragments
        int i = (int)(idx - 131072 - 2097152 - 131072);
        int nq = i >> 10, kc = (i >> 5) & 31, lane = i & 31;
        int col = nq * 16 + (lane >> 2);
        int kb  = kc * 32 + (lane & 3) * 4;
        const float* p0 = w3 + (size_t)col * 1024 + kb;
        const float* p1 = p0 + 8 * 1024;
        uint4 o;
        o.x = sgn4(p0); o.y = sgn4(p0 + 16);
        o.z = sgn4(p1); o.w = sgn4(p1 + 16);
        d_w3f[i] = o;
    } else if (idx < 131072 + 2097152 + 131072 + 32768 + 1024) { // w4 bitmasks
        int t = (int)(idx - 131072 - 2097152 - 131072 - 32768);
        int j = t >> 4, w = t & 15;
        unsigned p = 0, n = 0;
        #pragma unroll
        for (int i = 0; i < 32; i++) {
            float v = w4[j * 512 + w * 32 + i];
            if (v > 0.f) p |= (1u << i);
            if (v < 0.f) n |= (1u << i);
        }
        d_p4[j * 16 + w] = p;
        d_n4[j * 16 + w] = n;
    }
}

// ---------------- layer 1: bf16 mma GEMM (M=32768, N=2048, K=192) ----------------
#define L1_SMEM (49152 + 49152 + 3 * 512)
__global__ __launch_bounds__(256, 2) void l1mma_kernel(
    const float* __restrict__ b1, const float* __restrict__ g1,
    const float* __restrict__ be1, const float* __restrict__ m1,
    const float* __restrict__ v1)
{
    extern __shared__ __align__(128) char smem[];
    uint32_t sb = smem_u32(smem);
    float* ssc = (float*)(smem + 98304);
    float* sof = (float*)(smem + 98816);
    float* sbb = (float*)(smem + 99328);

    int tid = threadIdx.x, wid = tid >> 5, lane = tid & 31;
    int N0 = blockIdx.x * 128, R0 = blockIdx.y * 128;
    int warpM = (wid & 3) * 32, warpN = (wid >> 2) * 64;
    uint32_t ab = sb, bb = sb + 49152;

    const char* Ag = (const char*)(d_xp + (size_t)R0 * 192);
    const char* Wg = (const char*)(d_w1b + (size_t)N0 * 192);
    #pragma unroll
    for (int i = 0; i < 12; i++) {
        int idx = tid + i * 256;
        int r = idx / 24, sg = idx % 24;
        cp16(ab + swz384(r, sg), Ag + (size_t)r * 384 + sg * 16);
        cp16(bb + swz384(r, sg), Wg + (size_t)r * 384 + sg * 16);
    }
    asm volatile("cp.async.commit_group;");

    for (int t = tid; t < 128; t += 256) {
        int j = N0 + t;
        float sc = g1[j] / sqrtf(v1[j] + EPSBN);
        ssc[t] = sc;
        sof[t] = be1[j] - m1[j] * sc;
        sbb[t] = b1[j];
    }
    float C_[2][8][4];
    #pragma unroll
    for (int mt = 0; mt < 2; mt++)
        #pragma unroll
        for (int nt = 0; nt < 8; nt++)
            #pragma unroll
            for (int q = 0; q < 4; q++) C_[mt][nt][q] = 0.f;

    asm volatile("cp.async.wait_group 0;");
    __syncthreads();

    #pragma unroll
    for (int ks = 0; ks < 12; ks++) {
        uint32_t af[2][4];
        #pragma unroll
        for (int mt = 0; mt < 2; mt++) {
            int row = warpM + mt * 16 + (lane & 7) + ((lane >> 3) & 1) * 8;
            int sg  = ks * 2 + (lane >> 4);
            LDMX4(af[mt], ab + swz384(row, sg));
        }
        uint32_t bf[4][4];
        #pragma unroll
        for (int p = 0; p < 4; p++) {
            int row = warpN + p * 16 + (lane & 7) + (lane >> 4) * 8;
            int sg  = ks * 2 + ((lane >> 3) & 1);
            LDMX4(bf[p], bb + swz384(row, sg));
        }
        #pragma unroll
        for (int mt = 0; mt < 2; mt++)
            #pragma unroll
            for (int p = 0; p < 4; p++) {
                mma_bf16(C_[mt][2 * p],     af[mt], bf[p][0], bf[p][1]);
                mma_bf16(C_[mt][2 * p + 1], af[mt], bf[p][2], bf[p][3]);
            }
    }

    // epilogue: BN + threshold -> L2 A-fragments (KC = 64)
    #pragma unroll
    for (int mt = 0; mt < 2; mt++) {
        int rt = (R0 + warpM + mt * 16) >> 4;
        #pragma unroll
        for (int kc2 = 0; kc2 < 2; kc2++) {
            unsigned lo[4], hi[4];
            #pragma unroll
            for (int i = 0; i < 4; i++) {
                int nt = kc2 * 4 + i;
                int col = warpN + nt * 8 + (lane & 3) * 2;
                float sc0 = ssc[col],     of0 = sof[col],     bq0 = sbb[col];
                float sc1 = ssc[col + 1], of1 = sof[col + 1], bq1 = sbb[col + 1];
                unsigned b0 = (((C_[mt][nt][0] + bq0) * sc0 + of0) > 0.f) ? 1u : 0u;
                unsigned b1 = (((C_[mt][nt][1] + bq1) * sc1 + of1) > 0.f) ? 1u : 0u;
                unsigned b2 = (((C_[mt][nt][2] + bq0) * sc0 + of0) > 0.f) ? 1u : 0u;
                unsigned b3 = (((C_[mt][nt][3] + bq1) * sc1 + of1) > 0.f) ? 1u : 0u;
                lo[i] = b0 | (b1 << 8);
                hi[i] = b2 | (b3 << 8);
            }
            int kcg = ((N0 + warpN) >> 5) + kc2;
            emit_afrag(&d_a1f[((size_t)rt * 64 + kcg) * 32 + lane],
                       lo[0], lo[1], lo[2], lo[3], hi[0], hi[1], hi[2], hi[3], lane);
        }
    }
}

// ---------------- layers 2/3: s8 mma GEMM, rotated-K fragment mainloop -----------
template<int LAYER>
__global__ __launch_bounds__(256, 2) void mmas8_kernel(
    const float* __restrict__ bbp, const float* __restrict__ g,
    const float* __restrict__ be, const float* __restrict__ m,
    const float* __restrict__ v)
{
    constexpr int KDIM = (LAYER == 2) ? 2048 : 1024;
    constexpr int NOUT = (LAYER == 2) ? 1024 : 512;
    constexpr int KC   = KDIM / 32;
    const uint4* __restrict__ Af = (LAYER == 2) ? d_a1f : d_a2f;
    const uint4* __restrict__ Wf = (LAYER == 2) ? d_w2f : d_w3f;

    __shared__ float ssc[128], sof[128], sbb[128];

    int tid = threadIdx.x, wid = tid >> 5, lane = tid & 31;
    int N0 = blockIdx.x * 128, R0 = blockIdx.y * 128;
    int warpM = (wid & 3) * 32, warpN = (wid >> 2) * 64;

    if (tid < 128) {
        int j = N0 + tid;
        float sc = g[j] / sqrtf(v[j] + EPSBN);
        ssc[tid] = sc;
        sof[tid] = be[j] - m[j] * sc;
        sbb[tid] = bbp[j];
    }
    __syncthreads();

    int rt0 = (R0 + warpM) >> 4;
    int nq0 = (N0 + warpN) >> 4;
    const uint4* Ap0 = Af + ((size_t)rt0 * KC) * 32 + lane;
    const uint4* Ap1 = Af + ((size_t)(rt0 + 1) * KC) * 32 + lane;
    const uint4* Bp0 = Wf + ((size_t)nq0 * KC) * 32 + lane;
    const uint4* Bp1 = Wf + ((size_t)(nq0 + 1) * KC) * 32 + lane;
    const uint4* Bp2 = Wf + ((size_t)(nq0 + 2) * KC) * 32 + lane;
    const uint4* Bp3 = Wf + ((size_t)(nq0 + 3) * KC) * 32 + lane;

    int C_[2][8][4];
    #pragma unroll
    for (int mt = 0; mt < 2; mt++)
        #pragma unroll
        for (int nt = 0; nt < 8; nt++)
            #pragma unroll
            for (int q = 0; q < 4; q++) C_[mt][nt][q] = 0;

    // per-warp rotated K order: warp w starts at w*KC/8, wraps (integer sums
    // are order-independent -> bit-identical results, decorrelated LDG bursts)
    int kr = wid * (KC / 8);

    #pragma unroll 2
    for (int kci = 0; kci < KC; kci++) {
        int kc = (kci + kr) & (KC - 1);
        uint4 a0 = Ap0[kc * 32];
        uint4 a1 = Ap1[kc * 32];
        uint4 b0 = Bp0[kc * 32];
        uint4 b1 = Bp1[kc * 32];
        uint4 b2 = Bp2[kc * 32];
        uint4 b3 = Bp3[kc * 32];
        const uint32_t* A0 = (const uint32_t*)&a0;
        const uint32_t* A1 = (const uint32_t*)&a1;
        mma_s8(C_[0][0], A0, b0.x, b0.y);  mma_s8(C_[0][1], A0, b0.z, b0.w);
        mma_s8(C_[0][2], A0, b1.x, b1.y);  mma_s8(C_[0][3], A0, b1.z, b1.w);
        mma_s8(C_[0][4], A0, b2.x, b2.y);  mma_s8(C_[0][5], A0, b2.z, b2.w);
        mma_s8(C_[0][6], A0, b3.x, b3.y);  mma_s8(C_[0][7], A0, b3.z, b3.w);
        mma_s8(C_[1][0], A1, b0.x, b0.y);  mma_s8(C_[1][1], A1, b0.z, b0.w);
        mma_s8(C_[1][2], A1, b1.x, b1.y);  mma_s8(C_[1][3], A1, b1.z, b1.w);
        mma_s8(C_[1][4], A1, b2.x, b2.y);  mma_s8(C_[1][5], A1, b2.z, b2.w);
        mma_s8(C_[1][6], A1, b3.x, b3.y);  mma_s8(C_[1][7], A1, b3.z, b3.w);
    }

    if (LAYER == 2) {
        // epilogue: BN + threshold -> L3 A-fragments (KC_out = 32)
        #pragma unroll
        for (int mt = 0; mt < 2; mt++) {
            int rt = (R0 + warpM + mt * 16) >> 4;
            #pragma unroll
            for (int kc2 = 0; kc2 < 2; kc2++) {
                unsigned lo[4], hi[4];
                #pragma unroll
                for (int i = 0; i < 4; i++) {
                    int nt = kc2 * 4 + i;
                    int col = warpN + nt * 8 + (lane & 3) * 2;
                    float sc0 = ssc[col],     of0 = sof[col],     bq0 = sbb[col];
                    float sc1 = ssc[col + 1], of1 = sof[col + 1], bq1 = sbb[col + 1];
                    unsigned b0 = ((((float)C_[mt][nt][0] + bq0) * sc0 + of0) > 0.f) ? 1u : 0u;
                    unsigned b1 = ((((float)C_[mt][nt][1] + bq1) * sc1 + of1) > 0.f) ? 1u : 0u;
                    unsigned b2 = ((((float)C_[mt][nt][2] + bq0) * sc0 + of0) > 0.f) ? 1u : 0u;
                    unsigned b3 = ((((float)C_[mt][nt][3] + bq1) * sc1 + of1) > 0.f) ? 1u : 0u;
                    lo[i] = b0 | (b1 << 8);
                    hi[i] = b2 | (b3 << 8);
                }
                int kcg = ((N0 + warpN) >> 5) + kc2;
                emit_afrag(&d_a2f[((size_t)rt * 32 + kcg) * 32 + lane],
                           lo[0], lo[1], lo[2], lo[3], hi[0], hi[1], hi[2], hi[3], lane);
            }
        }
    } else {
        // epilogue: BN + threshold -> row-major s8 (for bitify)
        #pragma unroll
        for (int mt = 0; mt < 2; mt++)
            #pragma unroll
            for (int nt = 0; nt < 8; nt++) {
                int col = warpN + nt * 8 + (lane & 3) * 2;
                int r0  = R0 + warpM + mt * 16 + (lane >> 2);
                float sc0 = ssc[col],     of0 = sof[col],     bq0 = sbb[col];
                float sc1 = ssc[col + 1], of1 = sof[col + 1], bq1 = sbb[col + 1];
                char2 u;
                u.x = ((((float)C_[mt][nt][0] + bq0) * sc0 + of0) > 0.f) ? 1 : 0;
                u.y = ((((float)C_[mt][nt][1] + bq1) * sc1 + of1) > 0.f) ? 1 : 0;
                *(char2*)&d_a3s[(size_t)r0 * NOUT + N0 + col] = u;
                u.x = ((((float)C_[mt][nt][2] + bq0) * sc0 + of0) > 0.f) ? 1 : 0;
                u.y = ((((float)C_[mt][nt][3] + bq1) * sc1 + of1) > 0.f) ? 1 : 0;
                *(char2*)&d_a3s[(size_t)(r0 + 8) * NOUT + N0 + col] = u;
            }
    }
}

// ---------------- bitify layer-3 activations -------------------------------------
__global__ __launch_bounds__(256) void bitify_kernel() {
    int idx = blockIdx.x * 256 + threadIdx.x;            // 524288 threads
    const uint4* p = (const uint4*)d_a3s + (size_t)idx * 2;
    uint4 u0 = p[0], u1 = p[1];
    unsigned vs[8] = {u0.x, u0.y, u0.z, u0.w, u1.x, u1.y, u1.z, u1.w};
    unsigned w = 0;
    #pragma unroll
    for (int i = 0; i < 8; i++)
        w |= (((vs[i] & 0x01010101u) * 0x01020408u) >> 24) << (4 * i);
    d_h3[idx] = w;
}

// ---------------- layer 4 + layer 5 + sigmoid (fused popcount) -------------------
__global__ __launch_bounds__(128) void out_kernel(
    const float* __restrict__ b4, const float* __restrict__ g4,
    const float* __restrict__ be4, const float* __restrict__ m4,
    const float* __restrict__ v4, const float* __restrict__ w5,
    const float* __restrict__ b5, float* __restrict__ out)
{
    __shared__ unsigned p4s[64 * 16], n4s[64 * 16];
    __shared__ float sc4[64], off4[64], bb4[64], w5s[64];
    int tid = threadIdx.x;
    for (int i = tid; i < 1024; i += 128) { p4s[i] = d_p4[i]; n4s[i] = d_n4[i]; }
    if (tid < 64) {
        float sc = g4[tid] / sqrtf(v4[tid] + EPSBN);
        sc4[tid] = sc;
        off4[tid] = be4[tid] - m4[tid] * sc;
        bb4[tid]  = b4[tid];
        w5s[tid]  = w5[tid];
    }
    __syncthreads();

    int row = blockIdx.x * 128 + tid;
    unsigned h[16];
    #pragma unroll
    for (int q = 0; q < 4; q++) {
        uint4 t = *(const uint4*)&d_h3[(size_t)row * 16 + q * 4];
        h[q * 4] = t.x; h[q * 4 + 1] = t.y; h[q * 4 + 2] = t.z; h[q * 4 + 3] = t.w;
    }

    float z = b5[0];
    #pragma unroll 4
    for (int j = 0; j < 64; j++) {
        int a = 0, bn = 0;
        #pragma unroll
        for (int k = 0; k < 16; k++) {
            a  += __popc(h[k] & p4s[j * 16 + k]);
            bn += __popc(h[k] & n4s[j * 16 + k]);
        }
        float t = ((float)(a - bn) + bb4[j]) * sc4[j] + off4[j];
        if (t > 0.f) z += w5s[j];
    }
    out[row] = 1.f / (1.f + expf(-z));
}

// ---------------- launch ---------------------------------------------------------
extern "C" void kernel_launch(void* const* d_in, const int* in_sizes, int n_in,
                              void* d_out, int out_size) {
    const float* x   = (const float*)d_in[0];
    const float* w1  = (const float*)d_in[1];
    const float* b1  = (const float*)d_in[2];
    const float* w2  = (const float*)d_in[3];
    const float* b2  = (const float*)d_in[4];
    const float* w3  = (const float*)d_in[5];
    const float* b3  = (const float*)d_in[6];
    const float* w4  = (const float*)d_in[7];
    const float* b4  = (const float*)d_in[8];
    const float* w5  = (const float*)d_in[9];
    const float* b5  = (const float*)d_in[10];
    const float* g1  = (const float*)d_in[11];
    const float* be1 = (const float*)d_in[12];
    const float* m1  = (const float*)d_in[13];
    const float* v1  = (const float*)d_in[14];
    const float* g2  = (const float*)d_in[15];
    const float* be2 = (const float*)d_in[16];
    const float* m2  = (const float*)d_in[17];
    const float* v2  = (const float*)d_in[18];
    const float* g3  = (const float*)d_in[19];
    const float* be3 = (const float*)d_in[20];
    const float* m3  = (const float*)d_in[21];
    const float* v3  = (const float*)d_in[22];
    const float* g4  = (const float*)d_in[23];
    const float* be4 = (const float*)d_in[24];
    const float* m4  = (const float*)d_in[25];
    const float* v4  = (const float*)d_in[26];
    float* out = (float*)d_out;

    cudaFuncSetAttribute(l1mma_kernel, cudaFuncAttributeMaxDynamicSharedMemorySize, L1_SMEM);

    pack_all<<<9348, 256>>>(x, w1, w2, w3, w4);
    l1mma_kernel<<<dim3(16, 256), 256, L1_SMEM>>>(b1, g1, be1, m1, v1);
    mmas8_kernel<2><<<dim3(8, 256), 256>>>(b2, g2, be2, m2, v2);
    mmas8_kernel<3><<<dim3(4, 256), 256>>>(b3, g3, be3, m3, v3);
    bitify_kernel<<<2048, 256>>>();
    out_kernel<<<256, 128>>>(b4, g4, be4, m4, v4, w5, b5, out);
}